// round 14
// baseline (speedup 1.0000x reference)
#include <cuda_runtime.h>
#include <math.h>

#define BB 8
#define NN 16384
#define MM 128
#define CC 81
#define KPOS 128
#define BGCLS (CC - 1)
#define T 512
#define RNT (NN / T)     // 32 sweep iterations
#define BLKX (NN / T)    // 32 blocks per batch (512 preds each)

typedef unsigned int u32;
typedef unsigned short u16;

// ---------------- scratch ----------------
__device__ float g_miou[BB][NN];
__device__ int   g_match[BB][NN];
__device__ int   g_done[BB];        // zero-init; self-resetting
__device__ float g_part[BB][2];
__device__ unsigned g_ticket;       // zero-init; self-resetting

__device__ __forceinline__ u32 ford(float f) {
    u32 u = __float_as_uint(f);
    return (u & 0x80000000u) ? ~u : (u | 0x80000000u);
}
__device__ __forceinline__ u32 key_of(float mi, int kind) {
    bool pos = (mi >= 0.5f);
    if (kind == 0) { float sc = pos ? mi : -1.0f; return ~ford(sc); }
    return pos ? 0xFFFFFFFFu : ford(mi);
}

// 2048-bin scan + k-crossing (512 threads, 4 bins/thread)
__device__ __forceinline__ void scan_pick512(u32* hist, int k, int tid, int lane, int warp,
                                             int* s_w, int* sh_digit, int* sh_below) {
    int h[4], sum = 0;
    #pragma unroll
    for (int i = 0; i < 4; i++) { h[i] = (int)hist[4 * tid + i]; sum += h[i]; }
    int inc = sum;
    #pragma unroll
    for (int o = 1; o < 32; o <<= 1) {
        int nv = __shfl_up_sync(~0u, inc, o);
        if (lane >= o) inc += nv;
    }
    if (lane == 31) s_w[warp] = inc;
    __syncthreads();
    if (tid < 16) {
        int v = s_w[tid], e = v;
        #pragma unroll
        for (int o = 1; o < 16; o <<= 1) {
            int nv = __shfl_up_sync(0xFFFFu, e, o);
            if (tid >= o) e += nv;
        }
        s_w[tid] = e - v;
    }
    __syncthreads();
    int c = s_w[warp] + inc - sum;
    #pragma unroll
    for (int i = 0; i < 4; i++) {
        int c2 = c + h[i];
        if (c2 >= k && c < k) { *sh_digit = 4 * tid + i; *sh_below = c; }
        c = c2;
    }
    __syncthreads();
}

union Smem {
    struct { float4 g[MM]; float area[MM]; } iou;
    struct {
        u32 hist[2048];
        u16 cand[NN];
        u32 bmB[NN / 32];
        u32 bmE[NN / 32];
    } sel;
};

__global__ __launch_bounds__(T) void k_all(const float* __restrict__ bp,
                                           const float* __restrict__ cp,
                                           const float* __restrict__ rt,
                                           const int* __restrict__ labels,
                                           float* __restrict__ out) {
    __shared__ Smem sm;
    __shared__ int s_sel[256];
    __shared__ int s_w[16];
    __shared__ int sh_digit, sh_below;
    __shared__ int s_nc, s_ccnt, s_zcnt;
    __shared__ float s_c[16], s_r[16];
    __shared__ int s_islast;

    int b = blockIdx.y;
    int tid = threadIdx.x, lane = tid & 31, warp = tid >> 5;

    // ================= phase 1: IoU for this block's 512 preds =================
    if (tid < MM) {
        const float* v = rt + ((size_t)b * MM + tid) * 8;
        float x0 = v[0], y0 = v[1], x1 = v[2], y1 = v[3];
        float x2 = v[4], y2 = v[5], x3 = v[6], y3 = v[7];
        float mnx = fminf(fminf(x0, x1), fminf(x2, x3));
        float mny = fminf(fminf(y0, y1), fminf(y2, y3));
        float mxx = fmaxf(fmaxf(x0, x1), fmaxf(x2, x3));
        float mxy = fmaxf(fmaxf(y0, y1), fmaxf(y2, y3));
        sm.iou.g[tid] = make_float4(mnx, mny, mxx, mxy);
        sm.iou.area[tid] = (mxx - mnx) * (mxy - mny);
    }
    __syncthreads();

    {
        int n = blockIdx.x * T + tid;
        const float* p = bp + ((size_t)b * NN + n) * 5;
        float cx = p[0], cy = p[1], w = p[2], h = p[3], a = p[4];
        float c = cosf(a), s = sinf(a);
        float dx = w * 0.5f, dy = h * 0.5f;
        float xs0 = cx - dx * c + dy * s;
        float xs1 = cx + dx * c + dy * s;
        float xs2 = cx + dx * c - dy * s;
        float xs3 = cx - dx * c - dy * s;
        float ys0 = cy - dx * s - dy * c;
        float ys1 = cy + dx * s - dy * c;
        float ys2 = cy + dx * s + dy * c;
        float ys3 = cy - dx * s + dy * c;
        float pmnx = fminf(fminf(xs0, xs1), fminf(xs2, xs3));
        float pmxx = fmaxf(fmaxf(xs0, xs1), fmaxf(xs2, xs3));
        float pmny = fminf(fminf(ys0, ys1), fminf(ys2, ys3));
        float pmxy = fmaxf(fmaxf(ys0, ys1), fmaxf(ys2, ys3));
        float area_a = (pmxx - pmnx) * (pmxy - pmny);

        // 4 independent chains; iou monotone in inter/S (S = area_a + area_b > 0)
        float bi[4], bS[4];
        int bj[4];
        #pragma unroll
        for (int cc2 = 0; cc2 < 4; cc2++) { bi[cc2] = -1.0f; bS[cc2] = 1.0f; bj[cc2] = cc2 * 32; }
        #pragma unroll
        for (int cc2 = 0; cc2 < 4; cc2++) {
            int base = cc2 * 32;
            #pragma unroll 8
            for (int jj = 0; jj < 32; jj++) {
                int j = base + jj;
                float4 g = sm.iou.g[j];
                float iw = fmaxf(fminf(pmxx, g.z) - fmaxf(pmnx, g.x), 0.0f);
                float ih = fmaxf(fminf(pmxy, g.w) - fmaxf(pmny, g.y), 0.0f);
                float inter = iw * ih;
                float S = area_a + sm.iou.area[j];
                if (inter * bS[cc2] > bi[cc2] * S) { bi[cc2] = inter; bS[cc2] = S; bj[cc2] = j; }
            }
        }
        #pragma unroll
        for (int st = 1; st < 4; st <<= 1) {
            #pragma unroll
            for (int cc2 = 0; cc2 < 4; cc2 += 2 * st) {
                int o = cc2 + st;
                if (bi[o] * bS[cc2] > bi[cc2] * bS[o]) { bi[cc2] = bi[o]; bS[cc2] = bS[o]; bj[cc2] = bj[o]; }
            }
        }
        float un = bS[0] - bi[0];
        g_miou[b][n] = bi[0] / fmaxf(un, 1e-7f);   // reference rounding
        g_match[b][n] = bj[0];
    }

    // ================= handoff: last block of batch b proceeds =================
    __threadfence();
    __syncthreads();
    if (tid == 0) {
        int old = atomicAdd(&g_done[b], 1);
        s_islast = (old == BLKX - 1);
        if (s_islast) g_done[b] = 0;   // reset for next replay (all arrived)
    }
    __syncthreads();
    if (!s_islast) return;
    __threadfence();   // acquire side

    // ================= phase 2: top-128 select, both kinds =================
    for (int kind = 0; kind < 2; kind++) {
        u32 C = (kind == 0) ? ~ford(-1.0f) : 0xFFFFFFFFu;
        u32 Z = (kind == 0) ? C : ford(0.0f);

        for (int i = tid; i < 2048; i += T) sm.sel.hist[i] = 0;
        if (tid == 0) { s_nc = 0; s_ccnt = 0; s_zcnt = 0; }
        __syncthreads();

        int ccnt = 0, zcnt = 0;
        #pragma unroll
        for (int r = 0; r < RNT; r++) {
            int i = r * T + tid;
            u32 key = key_of(g_miou[b][i], kind);
            if (key == C) ccnt++;
            else if (key == Z) zcnt++;
            else atomicAdd(&sm.sel.hist[key >> 21], 1u);
        }
        #pragma unroll
        for (int o = 16; o; o >>= 1) {
            ccnt += __shfl_xor_sync(~0u, ccnt, o);
            zcnt += __shfl_xor_sync(~0u, zcnt, o);
        }
        if (lane == 0) {
            if (ccnt) { atomicAdd(&sm.sel.hist[C >> 21], (u32)ccnt); atomicAdd((u32*)&s_ccnt, (u32)ccnt); }
            if (zcnt) { atomicAdd(&sm.sel.hist[Z >> 21], (u32)zcnt); atomicAdd((u32*)&s_zcnt, (u32)zcnt); }
        }
        __syncthreads();

        int k = 128;
        scan_pick512(sm.sel.hist, k, tid, lane, warp, s_w, &sh_digit, &sh_below);
        u32 d1 = (u32)sh_digit;
        k -= sh_below;
        __syncthreads();

        int nonP = -1;
        u32 P = 0;
        if (d1 == (C >> 21))      { P = C; nonP = (int)sm.sel.hist[d1] - s_ccnt; }
        else if (d1 == (Z >> 21)) { P = Z; nonP = (int)sm.sel.hist[d1] - s_zcnt; }

        u32 t;
        if (nonP == 0) {
            t = P;   // pure-constant threshold bin (common case)
        } else {
            // general path: compact candidates of bin d1, radix passes 2-3
            #pragma unroll
            for (int r = 0; r < RNT; r++) {
                int i = r * T + tid;
                u32 key = key_of(g_miou[b][i], kind);
                bool w = ((key >> 21) == d1);
                unsigned ball = __ballot_sync(~0u, w);
                if (ball) {
                    int leader = __ffs(ball) - 1;
                    int base = 0;
                    if (lane == leader) base = atomicAdd(&s_nc, __popc(ball));
                    base = __shfl_sync(~0u, base, leader);
                    if (w) sm.sel.cand[base + __popc(ball & ((1u << lane) - 1u))] = (u16)i;
                }
            }
            __syncthreads();
            int nc = s_nc;

            for (int i = tid; i < 2048; i += T) sm.sel.hist[i] = 0;
            __syncthreads();
            for (int ci = tid; ci < nc; ci += T) {
                u32 key = key_of(g_miou[b][sm.sel.cand[ci]], kind);
                atomicAdd(&sm.sel.hist[(key >> 10) & 0x7FFu], 1u);
            }
            __syncthreads();
            scan_pick512(sm.sel.hist, k, tid, lane, warp, s_w, &sh_digit, &sh_below);
            u32 d2 = (u32)sh_digit;
            k -= sh_below;
            __syncthreads();

            for (int i = tid; i < 2048; i += T) sm.sel.hist[i] = 0;
            __syncthreads();
            u32 pref2 = (d1 << 21) | (d2 << 10);
            for (int ci = tid; ci < nc; ci += T) {
                u32 key = key_of(g_miou[b][sm.sel.cand[ci]], kind);
                if ((key & 0xFFFFFC00u) == pref2) atomicAdd(&sm.sel.hist[key & 0x3FFu], 1u);
            }
            __syncthreads();
            scan_pick512(sm.sel.hist, k, tid, lane, warp, s_w, &sh_digit, &sh_below);
            u32 d3 = (u32)sh_digit;
            k -= sh_below;
            __syncthreads();
            t = pref2 | d3;
        }

        int below_total = 128 - k;

        // one sweep: below + equals bitmasks (global index order)
        #pragma unroll
        for (int r = 0; r < RNT; r++) {
            int i = r * T + tid;
            u32 key = key_of(g_miou[b][i], kind);
            u32 ballB = __ballot_sync(~0u, key < t);
            u32 ballE = __ballot_sync(~0u, key == t);
            if (lane == 0) { sm.sel.bmB[r * 16 + warp] = ballB; sm.sel.bmE[r * 16 + warp] = ballE; }
        }
        __syncthreads();

        // below: exclusive scan over 512 words, owner emits
        {
            u32 wd = sm.sel.bmB[tid];
            int v = __popc(wd);
            int inc = v;
            #pragma unroll
            for (int o = 1; o < 32; o <<= 1) {
                int nv = __shfl_up_sync(~0u, inc, o);
                if (lane >= o) inc += nv;
            }
            if (lane == 31) s_w[warp] = inc;
            __syncthreads();
            if (tid < 16) {
                int vv = s_w[tid], e = vv;
                #pragma unroll
                for (int o = 1; o < 16; o <<= 1) {
                    int nv = __shfl_up_sync(0xFFFFu, e, o);
                    if (tid >= o) e += nv;
                }
                s_w[tid] = e - vv;
            }
            __syncthreads();
            int p = kind * 128 + s_w[warp] + inc - v;
            while (wd) {
                int bit = __ffs(wd) - 1; wd &= wd - 1;
                s_sel[p++] = tid * 32 + bit;
            }
        }
        __syncthreads();
        // equals: same scan, emit ascending-index until 128 filled
        {
            u32 wd = sm.sel.bmE[tid];
            int v = __popc(wd);
            int inc = v;
            #pragma unroll
            for (int o = 1; o < 32; o <<= 1) {
                int nv = __shfl_up_sync(~0u, inc, o);
                if (lane >= o) inc += nv;
            }
            if (lane == 31) s_w[warp] = inc;
            __syncthreads();
            if (tid < 16) {
                int vv = s_w[tid], e = vv;
                #pragma unroll
                for (int o = 1; o < 16; o <<= 1) {
                    int nv = __shfl_up_sync(0xFFFFu, e, o);
                    if (tid >= o) e += nv;
                }
                s_w[tid] = e - vv;
            }
            __syncthreads();
            int start = below_total + s_w[warp] + inc - v;
            while (wd && start < 128) {
                int bit = __ffs(wd) - 1; wd &= wd - 1;
                s_sel[kind * 128 + start++] = tid * 32 + bit;
            }
        }
        __syncthreads();
    }

    // ================= phase 3: loss over 256 samples (16 warps x 16) =========
    float cacc = 0.0f, racc = 0.0f;
    for (int q = 0; q < 16; q++) {
        int s = warp * 16 + q;
        int idx = s_sel[s];
        float miou = g_miou[b][idx];
        bool pos = (miou >= 0.5f);
        bool is_pos_slot = (s < KPOS);
        bool valid = is_pos_slot ? pos : (!pos);
        int m = g_match[b][idx];
        int tgt = pos ? labels[b * MM + m] : BGCLS;

        const float* lg = cp + ((size_t)b * NN + idx) * CC;
        float v0 = lg[lane];
        float v1 = (lane + 32 < CC) ? lg[lane + 32] : -INFINITY;
        float v2 = (lane + 64 < CC) ? lg[lane + 64] : -INFINITY;
        float mx = fmaxf(v0, fmaxf(v1, v2));
        #pragma unroll
        for (int o = 16; o; o >>= 1) mx = fmaxf(mx, __shfl_xor_sync(~0u, mx, o));
        float se = expf(v0 - mx);
        if (lane + 32 < CC) se += expf(v1 - mx);
        if (lane + 64 < CC) se += expf(v2 - mx);
        #pragma unroll
        for (int o = 16; o; o >>= 1) se += __shfl_xor_sync(~0u, se, o);

        if (lane == 0) {
            float nll = logf(se) + mx - __ldg(lg + tgt);
            cacc += valid ? nll : 0.0f;
            if (is_pos_slot && valid) {
                const float* v = rt + ((size_t)b * MM + m) * 8;
                float x0 = v[0], y0 = v[1], x1 = v[2], y1 = v[3];
                float x2 = v[4], y2 = v[5], x3 = v[6], y3 = v[7];
                float e1x = x1 - x0, e1y = y1 - y0;
                float e2x = x3 - x0, e2y = y3 - y0;
                float gb[5];
                gb[0] = (x0 + x1 + x2 + x3) * 0.25f;
                gb[1] = (y0 + y1 + y2 + y3) * 0.25f;
                gb[2] = sqrtf(e1x * e1x + e1y * e1y);
                gb[3] = sqrtf(e2x * e2x + e2y * e2y);
                gb[4] = atan2f(e1y, e1x);
                const float* pb = bp + ((size_t)b * NN + idx) * 5;
                float reg = 0.0f;
                #pragma unroll
                for (int d = 0; d < 5; d++) {
                    float ad = fabsf(pb[d] - gb[d]);
                    reg += (ad < 1.0f) ? 0.5f * ad * ad : ad - 0.5f;
                }
                racc += reg;
            }
        }
    }
    if (lane == 0) { s_c[warp] = cacc; s_r[warp] = racc; }
    __syncthreads();

    // ================= phase 4: per-batch partial + global combine ============
    if (tid == 0) {
        float cv = 0.0f, rv = 0.0f;
        #pragma unroll
        for (int j = 0; j < 16; j++) { cv += s_c[j]; rv += s_r[j]; }
        g_part[b][0] = cv;
        g_part[b][1] = rv;
        __threadfence();
        unsigned done = atomicAdd(&g_ticket, 1u);
        if (done == BB - 1) {
            __threadfence();
            float cs = 0.0f, rs = 0.0f;
            #pragma unroll
            for (int b2 = 0; b2 < BB; b2++) { cs += g_part[b2][0]; rs += g_part[b2][1]; }
            cs /= (float)BB;
            rs /= (float)BB;
            out[0] = cs + rs;
            out[1] = cs;
            out[2] = rs;
            g_ticket = 0;   // reset for next replay
        }
    }
}

// ---------------- launch ----------------
extern "C" void kernel_launch(void* const* d_in, const int* in_sizes, int n_in,
                              void* d_out, int out_size) {
    const float* box_pred   = (const float*)d_in[0];  // [8,16384,5]
    const float* class_pred = (const float*)d_in[1];  // [8,16384,81]
    const float* regr_tgt   = (const float*)d_in[2];  // [8,128,4,2]
    const int*   cls_tgt    = (const int*)d_in[3];    // [8,128]
    (void)in_sizes; (void)n_in; (void)out_size;

    k_all<<<dim3(BLKX, BB), T>>>(box_pred, class_pred, regr_tgt, cls_tgt,
                                 (float*)d_out);
}

// round 15
// speedup vs baseline: 2.0780x; 2.0780x over previous
#include <cuda_runtime.h>
#include <math.h>

#define BB 8
#define NN 16384
#define MM 128
#define CC 81
#define KPOS 128
#define BGCLS (CC - 1)
#define SEL_T 1024

typedef unsigned int u32;
typedef unsigned short u16;

// ---------------- scratch ----------------
__device__ float g_miou[BB][NN];
__device__ float g_part[BB][2][2];   // [batch][kind][cls,reg]
__device__ unsigned g_ticket;        // reset by k_iou each launch

__device__ __forceinline__ u32 ford(float f) {
    u32 u = __float_as_uint(f);
    return (u & 0x80000000u) ? ~u : (u | 0x80000000u);
}
__device__ __forceinline__ u32 key_of(float mi, int kind) {
    bool pos = (mi >= 0.5f);
    if (kind == 0) { float sc = pos ? mi : -1.0f; return ~ford(sc); }
    return pos ? 0xFFFFFFFFu : ford(mi);
}

// ---------------- K1: IoU max only (no argmax), 2 preds/thread ----------------
__global__ __launch_bounds__(256) void k_iou(const float* __restrict__ bp,
                                             const float* __restrict__ rt) {
    __shared__ float4 s_g[MM];
    __shared__ float  s_area[MM];
    int b = blockIdx.y;
    int tid = threadIdx.x;
    if (blockIdx.x == 0 && b == 0 && tid == 0) g_ticket = 0;
    if (tid < MM) {
        const float* v = rt + ((size_t)b * MM + tid) * 8;
        float x0 = v[0], y0 = v[1], x1 = v[2], y1 = v[3];
        float x2 = v[4], y2 = v[5], x3 = v[6], y3 = v[7];
        float mnx = fminf(fminf(x0, x1), fminf(x2, x3));
        float mny = fminf(fminf(y0, y1), fminf(y2, y3));
        float mxx = fmaxf(fmaxf(x0, x1), fmaxf(x2, x3));
        float mxy = fmaxf(fmaxf(y0, y1), fmaxf(y2, y3));
        s_g[tid] = make_float4(mnx, mny, mxx, mxy);
        s_area[tid] = (mxx - mnx) * (mxy - mny);
    }
    __syncthreads();

    int n0 = blockIdx.x * 512 + tid;
    int n1 = n0 + 256;

    float A_pmnx[2], A_pmxx[2], A_pmny[2], A_pmxy[2], A_area[2];
    #pragma unroll
    for (int q = 0; q < 2; q++) {
        int n = q ? n1 : n0;
        const float* p = bp + ((size_t)b * NN + n) * 5;
        float cx = p[0], cy = p[1], w = p[2], h = p[3], a = p[4];
        float c = cosf(a), s = sinf(a);
        float dx = w * 0.5f, dy = h * 0.5f;
        float xs0 = cx - dx * c + dy * s;
        float xs1 = cx + dx * c + dy * s;
        float xs2 = cx + dx * c - dy * s;
        float xs3 = cx - dx * c - dy * s;
        float ys0 = cy - dx * s - dy * c;
        float ys1 = cy + dx * s - dy * c;
        float ys2 = cy + dx * s + dy * c;
        float ys3 = cy - dx * s + dy * c;
        A_pmnx[q] = fminf(fminf(xs0, xs1), fminf(xs2, xs3));
        A_pmxx[q] = fmaxf(fmaxf(xs0, xs1), fmaxf(xs2, xs3));
        A_pmny[q] = fminf(fminf(ys0, ys1), fminf(ys2, ys3));
        A_pmxy[q] = fmaxf(fmaxf(ys0, ys1), fmaxf(ys2, ys3));
        A_area[q] = (A_pmxx[q] - A_pmnx[q]) * (A_pmxy[q] - A_pmny[q]);
    }

    // max of inter/S (iou = inter/(S-inter) monotone in inter/S); no index needed
    float bi[2][2], bS[2][2];
    #pragma unroll
    for (int q = 0; q < 2; q++)
        #pragma unroll
        for (int cc2 = 0; cc2 < 2; cc2++) { bi[q][cc2] = -1.0f; bS[q][cc2] = 1.0f; }

    #pragma unroll
    for (int half = 0; half < 2; half++) {
        int base = half * 64;
        #pragma unroll 8
        for (int jj = 0; jj < 64; jj++) {
            int j = base + jj;
            float4 g = s_g[j];
            float sa = s_area[j];
            #pragma unroll
            for (int q = 0; q < 2; q++) {
                float iw = fmaxf(fminf(A_pmxx[q], g.z) - fmaxf(A_pmnx[q], g.x), 0.0f);
                float ih = fmaxf(fminf(A_pmxy[q], g.w) - fmaxf(A_pmny[q], g.y), 0.0f);
                float inter = iw * ih;
                float S = A_area[q] + sa;
                if (inter * bS[q][half] > bi[q][half] * S) { bi[q][half] = inter; bS[q][half] = S; }
            }
        }
    }
    #pragma unroll
    for (int q = 0; q < 2; q++) {
        if (bi[q][1] * bS[q][0] > bi[q][0] * bS[q][1]) { bi[q][0] = bi[q][1]; bS[q][0] = bS[q][1]; }
        float un = bS[q][0] - bi[q][0];
        float best = bi[q][0] / fmaxf(un, 1e-7f);   // reference rounding
        g_miou[b][q ? n1 : n0] = best;
    }
}

// ---------------- scan helper: 2048 bins, 1024 threads ----------------
__device__ __forceinline__ void scan_pick(u32* hist, int k, int tid, int lane, int warp,
                                          int* s_w32, int* sh_digit, int* sh_below) {
    int h0 = (int)hist[2 * tid], h1 = (int)hist[2 * tid + 1];
    int sum2 = h0 + h1;
    int inc = sum2;
    #pragma unroll
    for (int o = 1; o < 32; o <<= 1) {
        int nv = __shfl_up_sync(~0u, inc, o);
        if (lane >= o) inc += nv;
    }
    if (lane == 31) s_w32[warp] = inc;
    __syncthreads();
    if (tid < 32) {
        int v = s_w32[lane];
        int e = v;
        #pragma unroll
        for (int o = 1; o < 32; o <<= 1) {
            int nv = __shfl_up_sync(~0u, e, o);
            if (lane >= o) e += nv;
        }
        s_w32[lane] = e - v;
    }
    __syncthreads();
    int excl = s_w32[warp] + inc - sum2;
    int c0 = excl + h0;
    int c1 = c0 + h1;
    if (c0 >= k && excl < k) { *sh_digit = 2 * tid;     *sh_below = excl; }
    if (c1 >= k && c0 < k)   { *sh_digit = 2 * tid + 1; *sh_below = c0; }
    __syncthreads();
}

// phase-sequenced smem reuse: cand -> bitmasks -> GT tables
union SelSmem {
    u16 cand[NN];                                  // general path only
    struct { u32 bmB[512]; u32 bmE[512]; } bm;     // after threshold known
    struct { float4 g[MM]; float area[MM]; } gt;   // argmax/loss phase
};

// ---------------- K2: select top-128 + loss for one (batch, kind) ----------------
__global__ __launch_bounds__(SEL_T) void k_selloss(const float* __restrict__ bp,
                                                   const float* __restrict__ cp,
                                                   const float* __restrict__ rt,
                                                   const int* __restrict__ labels,
                                                   float* __restrict__ out) {
    __shared__ u32 hist[2048];
    __shared__ SelSmem u;
    __shared__ int s_sel[128];
    __shared__ int s_w32[32];
    __shared__ int sh_digit, sh_below;
    __shared__ int s_nc, s_ccnt, s_zcnt;
    __shared__ float s_c[32], s_r[32];
    int b = blockIdx.y, kind = blockIdx.x;
    int tid = threadIdx.x, lane = tid & 31, warp = tid >> 5;

    u32 C = (kind == 0) ? ~ford(-1.0f) : 0xFFFFFFFFu;
    u32 Z = (kind == 0) ? C : ford(0.0f);

    hist[tid] = 0; hist[tid + 1024] = 0;
    if (tid == 0) { s_nc = 0; s_ccnt = 0; s_zcnt = 0; }
    __syncthreads();

    // build hist (top 11 bits); heavy constant keys warp-aggregated
    int ccnt = 0, zcnt = 0;
    #pragma unroll
    for (int r = 0; r < NN / SEL_T; r++) {
        u32 key = key_of(g_miou[b][r * SEL_T + tid], kind);
        if (key == C) ccnt++;
        else if (key == Z) zcnt++;
        else atomicAdd(&hist[key >> 21], 1u);
    }
    #pragma unroll
    for (int o = 16; o; o >>= 1) {
        ccnt += __shfl_xor_sync(~0u, ccnt, o);
        zcnt += __shfl_xor_sync(~0u, zcnt, o);
    }
    if (lane == 0) {
        if (ccnt) { atomicAdd(&hist[C >> 21], (u32)ccnt); atomicAdd((u32*)&s_ccnt, (u32)ccnt); }
        if (zcnt) { atomicAdd(&hist[Z >> 21], (u32)zcnt); atomicAdd((u32*)&s_zcnt, (u32)zcnt); }
    }
    __syncthreads();

    int k = 128;
    scan_pick(hist, k, tid, lane, warp, s_w32, &sh_digit, &sh_below);
    u32 d1 = (u32)sh_digit;
    k -= sh_below;
    __syncthreads();

    int nonP = -1;
    u32 P = 0;
    if (d1 == (C >> 21))      { P = C; nonP = (int)hist[d1] - s_ccnt; }
    else if (d1 == (Z >> 21)) { P = Z; nonP = (int)hist[d1] - s_zcnt; }

    u32 t;
    if (nonP == 0) {
        t = P;   // pure-constant threshold bin (common)
    } else {
        // general path: compact candidates, radix passes 2-3
        #pragma unroll
        for (int r = 0; r < NN / SEL_T; r++) {
            int i = r * SEL_T + tid;
            u32 key = key_of(g_miou[b][i], kind);
            bool w = ((key >> 21) == d1);
            unsigned ball = __ballot_sync(~0u, w);
            if (ball) {
                int leader = __ffs(ball) - 1;
                int base = 0;
                if (lane == leader) base = atomicAdd(&s_nc, __popc(ball));
                base = __shfl_sync(~0u, base, leader);
                if (w) u.cand[base + __popc(ball & ((1u << lane) - 1u))] = (u16)i;
            }
        }
        __syncthreads();
        int nc = s_nc;

        hist[tid] = 0; hist[tid + 1024] = 0;
        __syncthreads();
        for (int ci = tid; ci < nc; ci += SEL_T)
            atomicAdd(&hist[(key_of(g_miou[b][u.cand[ci]], kind) >> 10) & 0x7FFu], 1u);
        __syncthreads();
        scan_pick(hist, k, tid, lane, warp, s_w32, &sh_digit, &sh_below);
        u32 d2 = (u32)sh_digit;
        k -= sh_below;
        __syncthreads();

        hist[tid] = 0; hist[tid + 1024] = 0;
        __syncthreads();
        u32 pref2 = (d1 << 21) | (d2 << 10);
        for (int ci = tid; ci < nc; ci += SEL_T) {
            u32 key = key_of(g_miou[b][u.cand[ci]], kind);
            if ((key & 0xFFFFFC00u) == pref2) atomicAdd(&hist[key & 0x3FFu], 1u);
        }
        __syncthreads();
        scan_pick(hist, k, tid, lane, warp, s_w32, &sh_digit, &sh_below);
        u32 d3 = (u32)sh_digit;
        k -= sh_below;
        __syncthreads();
        t = pref2 | d3;
    }

    int below_total = 128 - k;
    __syncthreads();   // cand dead; bm phase begins

    // bitmask sweep (index order)
    #pragma unroll
    for (int r = 0; r < NN / SEL_T; r++) {
        int i = r * SEL_T + tid;
        u32 key = key_of(g_miou[b][i], kind);
        u32 ballB = __ballot_sync(~0u, key < t);
        u32 ballE = __ballot_sync(~0u, key == t);
        if (lane == 0) { u.bm.bmB[r * 32 + warp] = ballB; u.bm.bmE[r * 32 + warp] = ballE; }
    }
    __syncthreads();

    // dual exclusive scan: threads [0,512) below-words, [512,1024) equal-words
    bool isE = (tid >= 512);
    int w = tid & 511;
    u32 word = isE ? u.bm.bmE[w] : u.bm.bmB[w];
    int v = __popc(word);
    int inc = v;
    #pragma unroll
    for (int o = 1; o < 32; o <<= 1) {
        int nv = __shfl_up_sync(~0u, inc, o);
        if (lane >= o) inc += nv;
    }
    if (lane == 31) s_w32[warp] = inc;
    __syncthreads();
    if (tid < 32) {
        int vv = s_w32[tid];
        int e = vv;
        #pragma unroll
        for (int o = 1; o < 16; o <<= 1) {
            int nv = __shfl_up_sync(~0u, e, o);
            if ((tid & 15) >= o) e += nv;
        }
        s_w32[tid] = e - vv;
    }
    __syncthreads();
    int pcf = s_w32[warp] + inc - v;
    if (!isE) {
        int basep = pcf;
        u32 wd = word;
        while (wd) {
            int bit = __ffs(wd) - 1; wd &= wd - 1;
            s_sel[basep++] = w * 32 + bit;
        }
    } else {
        int start = below_total + pcf;
        if (start < 128) {
            u32 wd = word;
            while (wd && start < 128) {
                int bit = __ffs(wd) - 1; wd &= wd - 1;
                s_sel[start++] = w * 32 + bit;
            }
        }
    }
    __syncthreads();   // bm dead; gt phase begins

    // GT tables for argmax + loss
    if (tid < MM) {
        const float* vtx = rt + ((size_t)b * MM + tid) * 8;
        float x0 = vtx[0], y0 = vtx[1], x1 = vtx[2], y1 = vtx[3];
        float x2 = vtx[4], y2 = vtx[5], x3 = vtx[6], y3 = vtx[7];
        float mnx = fminf(fminf(x0, x1), fminf(x2, x3));
        float mny = fminf(fminf(y0, y1), fminf(y2, y3));
        float mxx = fmaxf(fmaxf(x0, x1), fmaxf(x2, x3));
        float mxy = fmaxf(fmaxf(y0, y1), fmaxf(y2, y3));
        u.gt.g[tid] = make_float4(mnx, mny, mxx, mxy);
        u.gt.area[tid] = (mxx - mnx) * (mxy - mny);
    }
    __syncthreads();

    // loss: 32 warps x 4 samples
    float cacc = 0.0f, racc = 0.0f;
    bool is_pos_slot = (kind == 0);
    #pragma unroll
    for (int q = 0; q < 4; q++) {
        int s = warp * 4 + q;
        int idx = s_sel[s];
        float miou = g_miou[b][idx];
        bool pos = (miou >= 0.5f);
        bool valid = is_pos_slot ? pos : (!pos);

        int m = 0;
        if (pos) {
            // warp-parallel argmax over 128 GT (smaller-index tie-break)
            const float* p = bp + ((size_t)b * NN + idx) * 5;
            float cx = p[0], cy = p[1], ww = p[2], hh = p[3], aa = p[4];
            float c = cosf(aa), sn = sinf(aa);
            float dx = ww * 0.5f, dy = hh * 0.5f;
            float xs0 = cx - dx * c + dy * sn;
            float xs1 = cx + dx * c + dy * sn;
            float xs2 = cx + dx * c - dy * sn;
            float xs3 = cx - dx * c - dy * sn;
            float ys0 = cy - dx * sn - dy * c;
            float ys1 = cy + dx * sn - dy * c;
            float ys2 = cy + dx * sn + dy * c;
            float ys3 = cy - dx * sn + dy * c;
            float pmnx = fminf(fminf(xs0, xs1), fminf(xs2, xs3));
            float pmxx = fmaxf(fmaxf(xs0, xs1), fmaxf(xs2, xs3));
            float pmny = fminf(fminf(ys0, ys1), fminf(ys2, ys3));
            float pmxy = fmaxf(fmaxf(ys0, ys1), fmaxf(ys2, ys3));
            float area_a = (pmxx - pmnx) * (pmxy - pmny);
            float bi = 0.0f, bS = 1.0f;
            int bj = MM;
            #pragma unroll
            for (int rr = 0; rr < 4; rr++) {
                int j = rr * 32 + lane;
                float4 g = u.gt.g[j];
                float iw = fmaxf(fminf(pmxx, g.z) - fmaxf(pmnx, g.x), 0.0f);
                float ih = fmaxf(fminf(pmxy, g.w) - fmaxf(pmny, g.y), 0.0f);
                float inter = iw * ih;
                float S = area_a + u.gt.area[j];
                if (inter * bS > bi * S) { bi = inter; bS = S; bj = j; }
            }
            #pragma unroll
            for (int o = 16; o; o >>= 1) {
                float bi2 = __shfl_xor_sync(~0u, bi, o);
                float bS2 = __shfl_xor_sync(~0u, bS, o);
                int   bj2 = __shfl_xor_sync(~0u, bj, o);
                float p2 = bi2 * bS, p1 = bi * bS2;
                if (p2 > p1 || (p2 == p1 && bj2 < bj)) { bi = bi2; bS = bS2; bj = bj2; }
            }
            m = bj;
        }
        int tgt = pos ? labels[b * MM + m] : BGCLS;

        const float* lg = cp + ((size_t)b * NN + idx) * CC;
        float v0 = lg[lane];
        float v1 = (lane + 32 < CC) ? lg[lane + 32] : -INFINITY;
        float v2 = (lane + 64 < CC) ? lg[lane + 64] : -INFINITY;
        float mx = fmaxf(v0, fmaxf(v1, v2));
        #pragma unroll
        for (int o = 16; o; o >>= 1) mx = fmaxf(mx, __shfl_xor_sync(~0u, mx, o));
        float se = expf(v0 - mx);
        if (lane + 32 < CC) se += expf(v1 - mx);
        if (lane + 64 < CC) se += expf(v2 - mx);
        #pragma unroll
        for (int o = 16; o; o >>= 1) se += __shfl_xor_sync(~0u, se, o);

        if (lane == 0) {
            float nll = logf(se) + mx - __ldg(lg + tgt);
            cacc += valid ? nll : 0.0f;
            if (is_pos_slot && valid) {
                const float* vtx = rt + ((size_t)b * MM + m) * 8;
                float x0 = vtx[0], y0 = vtx[1], x1 = vtx[2], y1 = vtx[3];
                float x2 = vtx[4], y2 = vtx[5], x3 = vtx[6], y3 = vtx[7];
                float e1x = x1 - x0, e1y = y1 - y0;
                float e2x = x3 - x0, e2y = y3 - y0;
                float gb[5];
                gb[0] = (x0 + x1 + x2 + x3) * 0.25f;
                gb[1] = (y0 + y1 + y2 + y3) * 0.25f;
                gb[2] = sqrtf(e1x * e1x + e1y * e1y);
                gb[3] = sqrtf(e2x * e2x + e2y * e2y);
                gb[4] = atan2f(e1y, e1x);
                const float* pb = bp + ((size_t)b * NN + idx) * 5;
                float reg = 0.0f;
                #pragma unroll
                for (int d = 0; d < 5; d++) {
                    float ad = fabsf(pb[d] - gb[d]);
                    reg += (ad < 1.0f) ? 0.5f * ad * ad : ad - 0.5f;
                }
                racc += reg;
            }
        }
    }
    if (lane == 0) { s_c[warp] = cacc; s_r[warp] = racc; }
    __syncthreads();

    if (tid == 0) {
        float cv = 0.0f, rv = 0.0f;
        #pragma unroll
        for (int j = 0; j < 32; j++) { cv += s_c[j]; rv += s_r[j]; }
        g_part[b][kind][0] = cv;
        g_part[b][kind][1] = rv;
        __threadfence();
        unsigned done = atomicAdd(&g_ticket, 1u);
        if (done == 2 * BB - 1) {
            __threadfence();
            float cs = 0.0f, rs = 0.0f;
            #pragma unroll
            for (int b2 = 0; b2 < BB; b2++) {
                cs += g_part[b2][0][0] + g_part[b2][1][0];
                rs += g_part[b2][0][1] + g_part[b2][1][1];
            }
            cs /= (float)BB;
            rs /= (float)BB;
            out[0] = cs + rs;
            out[1] = cs;
            out[2] = rs;
        }
    }
}

// ---------------- launch ----------------
extern "C" void kernel_launch(void* const* d_in, const int* in_sizes, int n_in,
                              void* d_out, int out_size) {
    const float* box_pred   = (const float*)d_in[0];  // [8,16384,5]
    const float* class_pred = (const float*)d_in[1];  // [8,16384,81]
    const float* regr_tgt   = (const float*)d_in[2];  // [8,128,4,2]
    const int*   cls_tgt    = (const int*)d_in[3];    // [8,128]
    (void)in_sizes; (void)n_in; (void)out_size;

    k_iou<<<dim3(NN / 512, BB), 256>>>(box_pred, regr_tgt);
    k_selloss<<<dim3(2, BB), SEL_T>>>(box_pred, class_pred, regr_tgt, cls_tgt,
                                      (float*)d_out);
}

// round 16
// speedup vs baseline: 2.4221x; 1.1656x over previous
#include <cuda_runtime.h>
#include <math.h>

#define BB 8
#define NN 16384
#define MM 128
#define CC 81
#define KPOS 128
#define NSAMP 256
#define BGCLS (CC - 1)
#define SEL_T 1024
#define LOSS_BX 32
#define NPART (LOSS_BX)

typedef unsigned int u32;
typedef unsigned short u16;

// ---------------- scratch ----------------
__device__ float g_miou[BB][NN];
__device__ int   g_selidx[BB][NSAMP];
__device__ float g_part[BB][NPART][2];
__device__ unsigned g_ticket;

__device__ __forceinline__ u32 ford(float f) {
    u32 u = __float_as_uint(f);
    return (u & 0x80000000u) ? ~u : (u | 0x80000000u);
}
__device__ __forceinline__ u32 key_of(float mi, int kind) {
    bool pos = (mi >= 0.5f);
    if (kind == 0) { float sc = pos ? mi : -1.0f; return ~ford(sc); }
    return pos ? 0xFFFFFFFFu : ford(mi);
}

// ---------------- K1: IoU max only (no argmax), 2 preds/thread ----------------
__global__ __launch_bounds__(256) void k_iou(const float* __restrict__ bp,
                                             const float* __restrict__ rt) {
    __shared__ float4 s_g[MM];
    __shared__ float  s_area[MM];
    int b = blockIdx.y;
    int tid = threadIdx.x;
    if (blockIdx.x == 0 && b == 0 && tid == 0) g_ticket = 0;
    if (tid < MM) {
        const float* v = rt + ((size_t)b * MM + tid) * 8;
        float x0 = v[0], y0 = v[1], x1 = v[2], y1 = v[3];
        float x2 = v[4], y2 = v[5], x3 = v[6], y3 = v[7];
        float mnx = fminf(fminf(x0, x1), fminf(x2, x3));
        float mny = fminf(fminf(y0, y1), fminf(y2, y3));
        float mxx = fmaxf(fmaxf(x0, x1), fmaxf(x2, x3));
        float mxy = fmaxf(fmaxf(y0, y1), fmaxf(y2, y3));
        s_g[tid] = make_float4(mnx, mny, mxx, mxy);
        s_area[tid] = (mxx - mnx) * (mxy - mny);
    }
    __syncthreads();

    int n0 = blockIdx.x * 512 + tid;
    int n1 = n0 + 256;

    float A_pmnx[2], A_pmxx[2], A_pmny[2], A_pmxy[2], A_area[2];
    #pragma unroll
    for (int q = 0; q < 2; q++) {
        int n = q ? n1 : n0;
        const float* p = bp + ((size_t)b * NN + n) * 5;
        float cx = p[0], cy = p[1], w = p[2], h = p[3], a = p[4];
        float c = cosf(a), s = sinf(a);
        float dx = w * 0.5f, dy = h * 0.5f;
        float xs0 = cx - dx * c + dy * s;
        float xs1 = cx + dx * c + dy * s;
        float xs2 = cx + dx * c - dy * s;
        float xs3 = cx - dx * c - dy * s;
        float ys0 = cy - dx * s - dy * c;
        float ys1 = cy + dx * s - dy * c;
        float ys2 = cy + dx * s + dy * c;
        float ys3 = cy - dx * s + dy * c;
        A_pmnx[q] = fminf(fminf(xs0, xs1), fminf(xs2, xs3));
        A_pmxx[q] = fmaxf(fmaxf(xs0, xs1), fmaxf(xs2, xs3));
        A_pmny[q] = fminf(fminf(ys0, ys1), fminf(ys2, ys3));
        A_pmxy[q] = fmaxf(fmaxf(ys0, ys1), fmaxf(ys2, ys3));
        A_area[q] = (A_pmxx[q] - A_pmnx[q]) * (A_pmxy[q] - A_pmny[q]);
    }

    // max of inter/S (iou = inter/(S-inter) monotone in inter/S); no index tracking
    float bi[2][2], bS[2][2];
    #pragma unroll
    for (int q = 0; q < 2; q++)
        #pragma unroll
        for (int cc2 = 0; cc2 < 2; cc2++) { bi[q][cc2] = -1.0f; bS[q][cc2] = 1.0f; }

    #pragma unroll
    for (int half = 0; half < 2; half++) {
        int base = half * 64;
        #pragma unroll 8
        for (int jj = 0; jj < 64; jj++) {
            int j = base + jj;
            float4 g = s_g[j];
            float sa = s_area[j];
            #pragma unroll
            for (int q = 0; q < 2; q++) {
                float iw = fmaxf(fminf(A_pmxx[q], g.z) - fmaxf(A_pmnx[q], g.x), 0.0f);
                float ih = fmaxf(fminf(A_pmxy[q], g.w) - fmaxf(A_pmny[q], g.y), 0.0f);
                float inter = iw * ih;
                float S = A_area[q] + sa;
                if (inter * bS[q][half] > bi[q][half] * S) { bi[q][half] = inter; bS[q][half] = S; }
            }
        }
    }
    #pragma unroll
    for (int q = 0; q < 2; q++) {
        if (bi[q][1] * bS[q][0] > bi[q][0] * bS[q][1]) { bi[q][0] = bi[q][1]; bS[q][0] = bS[q][1]; }
        float un = bS[q][0] - bi[q][0];
        float best = bi[q][0] / fmaxf(un, 1e-7f);   // reference rounding
        g_miou[b][q ? n1 : n0] = best;
    }
}

// ---------------- scan helper: 2048 bins, 1024 threads ----------------
__device__ __forceinline__ void scan_pick(u32* hist, int k, int tid, int lane, int warp,
                                          int* s_w32, int* sh_digit, int* sh_below) {
    int h0 = (int)hist[2 * tid], h1 = (int)hist[2 * tid + 1];
    int sum2 = h0 + h1;
    int inc = sum2;
    #pragma unroll
    for (int o = 1; o < 32; o <<= 1) {
        int nv = __shfl_up_sync(~0u, inc, o);
        if (lane >= o) inc += nv;
    }
    if (lane == 31) s_w32[warp] = inc;
    __syncthreads();
    if (tid < 32) {
        int v = s_w32[lane];
        int e = v;
        #pragma unroll
        for (int o = 1; o < 32; o <<= 1) {
            int nv = __shfl_up_sync(~0u, e, o);
            if (lane >= o) e += nv;
        }
        s_w32[lane] = e - v;
    }
    __syncthreads();
    int excl = s_w32[warp] + inc - sum2;
    int c0 = excl + h0;
    int c1 = c0 + h1;
    if (c0 >= k && excl < k) { *sh_digit = 2 * tid;     *sh_below = excl; }
    if (c1 >= k && c0 < k)   { *sh_digit = 2 * tid + 1; *sh_below = c0; }
    __syncthreads();
}

// ---------------- K2: exact top-128 radix select (R13 v5, smem key cache) ----------------
extern __shared__ u32 sk32[];  // NN keys = 64KB dynamic
__global__ __launch_bounds__(SEL_T) void k_select() {
    __shared__ u32 hist[2048];
    __shared__ u16 cand[NN];
    __shared__ u32 bmB[512], bmE[512];
    __shared__ int s_w32[32];
    __shared__ int s_sums[32];
    __shared__ int sh_digit, sh_below;
    __shared__ int s_nc, s_ccnt, s_zcnt;
    int b = blockIdx.x >> 1, kind = blockIdx.x & 1;
    int tid = threadIdx.x, lane = tid & 31, warp = tid >> 5;

    u32 C = (kind == 0) ? ~ford(-1.0f) : 0xFFFFFFFFu;
    u32 Z = (kind == 0) ? C : ford(0.0f);

    hist[tid] = 0; hist[tid + 1024] = 0;
    if (tid == 0) { s_nc = 0; s_ccnt = 0; s_zcnt = 0; }
    __syncthreads();

    int ccnt = 0, zcnt = 0;
    #pragma unroll
    for (int r = 0; r < NN / SEL_T; r++) {
        int i = r * SEL_T + tid;
        u32 key = key_of(g_miou[b][i], kind);
        sk32[i] = key;
        if (key == C) ccnt++;
        else if (key == Z) zcnt++;
        else atomicAdd(&hist[key >> 21], 1u);
    }
    #pragma unroll
    for (int o = 16; o; o >>= 1) {
        ccnt += __shfl_xor_sync(~0u, ccnt, o);
        zcnt += __shfl_xor_sync(~0u, zcnt, o);
    }
    if (lane == 0) {
        if (ccnt) { atomicAdd(&hist[C >> 21], (u32)ccnt); atomicAdd((u32*)&s_ccnt, (u32)ccnt); }
        if (zcnt) { atomicAdd(&hist[Z >> 21], (u32)zcnt); atomicAdd((u32*)&s_zcnt, (u32)zcnt); }
    }
    __syncthreads();

    int k = 128;
    scan_pick(hist, k, tid, lane, warp, s_w32, &sh_digit, &sh_below);
    u32 d1 = (u32)sh_digit;
    k -= sh_below;
    __syncthreads();

    int nonP = -1;
    u32 P = 0;
    if (d1 == (C >> 21))      { P = C; nonP = (int)hist[d1] - s_ccnt; }
    else if (d1 == (Z >> 21)) { P = Z; nonP = (int)hist[d1] - s_zcnt; }

    u32 t;
    if (nonP == 0) {
        t = P;
    } else {
        #pragma unroll
        for (int r = 0; r < NN / SEL_T; r++) {
            int i = r * SEL_T + tid;
            u32 key = sk32[i];
            bool w = ((key >> 21) == d1);
            unsigned ball = __ballot_sync(~0u, w);
            if (ball) {
                int leader = __ffs(ball) - 1;
                int base = 0;
                if (lane == leader) base = atomicAdd(&s_nc, __popc(ball));
                base = __shfl_sync(~0u, base, leader);
                if (w) cand[base + __popc(ball & ((1u << lane) - 1u))] = (u16)i;
            }
        }
        __syncthreads();
        int nc = s_nc;

        hist[tid] = 0; hist[tid + 1024] = 0;
        __syncthreads();
        for (int ci = tid; ci < nc; ci += SEL_T)
            atomicAdd(&hist[(sk32[cand[ci]] >> 10) & 0x7FFu], 1u);
        __syncthreads();
        scan_pick(hist, k, tid, lane, warp, s_w32, &sh_digit, &sh_below);
        u32 d2 = (u32)sh_digit;
        k -= sh_below;
        __syncthreads();

        hist[tid] = 0; hist[tid + 1024] = 0;
        __syncthreads();
        u32 pref2 = (d1 << 21) | (d2 << 10);
        for (int ci = tid; ci < nc; ci += SEL_T) {
            u32 key = sk32[cand[ci]];
            if ((key & 0xFFFFFC00u) == pref2) atomicAdd(&hist[key & 0x3FFu], 1u);
        }
        __syncthreads();
        scan_pick(hist, k, tid, lane, warp, s_w32, &sh_digit, &sh_below);
        u32 d3 = (u32)sh_digit;
        k -= sh_below;
        __syncthreads();
        t = pref2 | d3;
    }

    int below_total = 128 - k;

    #pragma unroll
    for (int r = 0; r < NN / SEL_T; r++) {
        int i = r * SEL_T + tid;
        u32 key = sk32[i];
        u32 ballB = __ballot_sync(~0u, key < t);
        u32 ballE = __ballot_sync(~0u, key == t);
        if (lane == 0) { bmB[r * 32 + warp] = ballB; bmE[r * 32 + warp] = ballE; }
    }
    __syncthreads();

    bool isE = (tid >= 512);
    int w = tid & 511;
    u32 word = isE ? bmE[w] : bmB[w];
    int v = __popc(word);
    int inc = v;
    #pragma unroll
    for (int o = 1; o < 32; o <<= 1) {
        int nv = __shfl_up_sync(~0u, inc, o);
        if (lane >= o) inc += nv;
    }
    if (lane == 31) s_sums[warp] = inc;
    __syncthreads();
    if (tid < 32) {
        int vv = s_sums[tid];
        int e = vv;
        #pragma unroll
        for (int o = 1; o < 16; o <<= 1) {
            int nv = __shfl_up_sync(~0u, e, o);
            if ((tid & 15) >= o) e += nv;
        }
        s_sums[tid] = e - vv;
    }
    __syncthreads();
    int pc = s_sums[warp] + inc - v;

    int sel_base = kind * 128;
    if (!isE) {
        int basep = pc;
        u32 wd = word;
        while (wd) {
            int bit = __ffs(wd) - 1; wd &= wd - 1;
            g_selidx[b][sel_base + basep++] = w * 32 + bit;
        }
    } else {
        int start = below_total + pc;
        if (start < 128) {
            u32 wd = word;
            while (wd && start < 128) {
                int bit = __ffs(wd) - 1; wd &= wd - 1;
                g_selidx[b][sel_base + start++] = w * 32 + bit;
            }
        }
    }
}

// ---------------- K3: warp-per-sample loss + argmax recompute + final combine ---
__global__ __launch_bounds__(256) void k_loss(const float* __restrict__ bp,
                                              const float* __restrict__ cp,
                                              const float* __restrict__ rt,
                                              const int* __restrict__ labels,
                                              float* __restrict__ out) {
    __shared__ float4 s_g[MM];
    __shared__ float  s_area[MM];
    __shared__ float s_c[8], s_r[8];
    __shared__ float s_fc[256], s_fr[256];
    __shared__ bool s_last;
    int b = blockIdx.y;
    int w = threadIdx.x >> 5, lane = threadIdx.x & 31;
    int tid = threadIdx.x;

    // GT AABB table (for argmax recompute)
    if (tid < MM) {
        const float* vtx = rt + ((size_t)b * MM + tid) * 8;
        float x0 = vtx[0], y0 = vtx[1], x1 = vtx[2], y1 = vtx[3];
        float x2 = vtx[4], y2 = vtx[5], x3 = vtx[6], y3 = vtx[7];
        float mnx = fminf(fminf(x0, x1), fminf(x2, x3));
        float mny = fminf(fminf(y0, y1), fminf(y2, y3));
        float mxx = fmaxf(fmaxf(x0, x1), fmaxf(x2, x3));
        float mxy = fmaxf(fmaxf(y0, y1), fmaxf(y2, y3));
        s_g[tid] = make_float4(mnx, mny, mxx, mxy);
        s_area[tid] = (mxx - mnx) * (mxy - mny);
    }
    __syncthreads();

    int s = blockIdx.x * 8 + w;
    int idx = g_selidx[b][s];
    float miou = g_miou[b][idx];
    bool pos = (miou >= 0.5f);
    bool is_pos_slot = (s < KPOS);
    bool valid = is_pos_slot ? pos : (!pos);

    // argmax recompute (warp-parallel, 4 GT/lane, smaller-index tie-break)
    int m = 0;
    if (pos) {
        const float* p = bp + ((size_t)b * NN + idx) * 5;
        float cx = p[0], cy = p[1], ww = p[2], hh = p[3], aa = p[4];
        float c = cosf(aa), sn = sinf(aa);
        float dx = ww * 0.5f, dy = hh * 0.5f;
        float xs0 = cx - dx * c + dy * sn;
        float xs1 = cx + dx * c + dy * sn;
        float xs2 = cx + dx * c - dy * sn;
        float xs3 = cx - dx * c - dy * sn;
        float ys0 = cy - dx * sn - dy * c;
        float ys1 = cy + dx * sn - dy * c;
        float ys2 = cy + dx * sn + dy * c;
        float ys3 = cy - dx * sn + dy * c;
        float pmnx = fminf(fminf(xs0, xs1), fminf(xs2, xs3));
        float pmxx = fmaxf(fmaxf(xs0, xs1), fmaxf(xs2, xs3));
        float pmny = fminf(fminf(ys0, ys1), fminf(ys2, ys3));
        float pmxy = fmaxf(fmaxf(ys0, ys1), fmaxf(ys2, ys3));
        float area_a = (pmxx - pmnx) * (pmxy - pmny);
        float bi = 0.0f, bS = 1.0f;
        int bj = MM;
        #pragma unroll
        for (int rr = 0; rr < 4; rr++) {
            int j = rr * 32 + lane;
            float4 g = s_g[j];
            float iw = fmaxf(fminf(pmxx, g.z) - fmaxf(pmnx, g.x), 0.0f);
            float ih = fmaxf(fminf(pmxy, g.w) - fmaxf(pmny, g.y), 0.0f);
            float inter = iw * ih;
            float S = area_a + s_area[j];
            if (inter * bS > bi * S) { bi = inter; bS = S; bj = j; }
        }
        #pragma unroll
        for (int o = 16; o; o >>= 1) {
            float bi2 = __shfl_xor_sync(~0u, bi, o);
            float bS2 = __shfl_xor_sync(~0u, bS, o);
            int   bj2 = __shfl_xor_sync(~0u, bj, o);
            float p2 = bi2 * bS, p1 = bi * bS2;
            if (p2 > p1 || (p2 == p1 && bj2 < bj)) { bi = bi2; bS = bS2; bj = bj2; }
        }
        m = bj;
    }
    int tgt = pos ? labels[b * MM + m] : BGCLS;

    const float* lg = cp + ((size_t)b * NN + idx) * CC;
    float v0 = lg[lane];
    float v1 = (lane + 32 < CC) ? lg[lane + 32] : -INFINITY;
    float v2 = (lane + 64 < CC) ? lg[lane + 64] : -INFINITY;
    float mx = fmaxf(v0, fmaxf(v1, v2));
    #pragma unroll
    for (int o = 16; o; o >>= 1) mx = fmaxf(mx, __shfl_xor_sync(~0u, mx, o));
    float se = expf(v0 - mx);
    if (lane + 32 < CC) se += expf(v1 - mx);
    if (lane + 64 < CC) se += expf(v2 - mx);
    #pragma unroll
    for (int o = 16; o; o >>= 1) se += __shfl_xor_sync(~0u, se, o);

    if (lane == 0) {
        float nll = logf(se) + mx - __ldg(lg + tgt);
        s_c[w] = valid ? nll : 0.0f;
        float reg = 0.0f;
        if (is_pos_slot && valid) {
            const float* vtx = rt + ((size_t)b * MM + m) * 8;
            float x0 = vtx[0], y0 = vtx[1], x1 = vtx[2], y1 = vtx[3];
            float x2 = vtx[4], y2 = vtx[5], x3 = vtx[6], y3 = vtx[7];
            float e1x = x1 - x0, e1y = y1 - y0;
            float e2x = x3 - x0, e2y = y3 - y0;
            float gb[5];
            gb[0] = (x0 + x1 + x2 + x3) * 0.25f;
            gb[1] = (y0 + y1 + y2 + y3) * 0.25f;
            gb[2] = sqrtf(e1x * e1x + e1y * e1y);
            gb[3] = sqrtf(e2x * e2x + e2y * e2y);
            gb[4] = atan2f(e1y, e1x);
            const float* pb = bp + ((size_t)b * NN + idx) * 5;
            #pragma unroll
            for (int d = 0; d < 5; d++) {
                float ad = fabsf(pb[d] - gb[d]);
                reg += (ad < 1.0f) ? 0.5f * ad * ad : ad - 0.5f;
            }
        }
        s_r[w] = reg;
    }
    __syncthreads();
    if (tid == 0) {
        float cv = 0.0f, rv = 0.0f;
        #pragma unroll
        for (int j = 0; j < 8; j++) { cv += s_c[j]; rv += s_r[j]; }
        g_part[b][blockIdx.x][0] = cv;
        g_part[b][blockIdx.x][1] = rv;
        __threadfence();
        unsigned done = atomicAdd(&g_ticket, 1u);
        s_last = (done == (unsigned)(BB * NPART - 1));
    }
    __syncthreads();
    if (s_last) {
        const float* gp = &g_part[0][0][0];
        int t = tid;
        s_fc[t] = gp[2 * t];
        s_fr[t] = gp[2 * t + 1];
        __syncthreads();
        for (int st = 128; st > 0; st >>= 1) {
            if (t < st) { s_fc[t] += s_fc[t + st]; s_fr[t] += s_fr[t + st]; }
            __syncthreads();
        }
        if (t == 0) {
            float cs = s_fc[0] / (float)BB;
            float rs = s_fr[0] / (float)BB;
            out[0] = cs + rs;
            out[1] = cs;
            out[2] = rs;
        }
    }
}

// ---------------- launch ----------------
extern "C" void kernel_launch(void* const* d_in, const int* in_sizes, int n_in,
                              void* d_out, int out_size) {
    const float* box_pred   = (const float*)d_in[0];
    const float* class_pred = (const float*)d_in[1];
    const float* regr_tgt   = (const float*)d_in[2];
    const int*   cls_tgt    = (const int*)d_in[3];
    (void)in_sizes; (void)n_in; (void)out_size;

    cudaFuncSetAttribute(k_select, cudaFuncAttributeMaxDynamicSharedMemorySize,
                         NN * (int)sizeof(u32));

    k_iou<<<dim3(NN / 512, BB), 256>>>(box_pred, regr_tgt);
    k_select<<<2 * BB, SEL_T, NN * sizeof(u32)>>>();
    k_loss<<<dim3(LOSS_BX, BB), 256>>>(box_pred, class_pred, regr_tgt, cls_tgt,
                                       (float*)d_out);
}